// round 2
// baseline (speedup 1.0000x reference)
#include <cuda_runtime.h>
#include <math.h>

#define Bq 8
#define Tq 4096
#define Dq 896
#define Sq 64
#define NTH 1024

#define GM (Bq*Tq)   // 32768
#define GN Dq        // 896
#define GK Dq        // 896

// scratch: normalized m for every (b,t), consumed by the batched GEMM
__device__ float g_mn[(size_t)Bq * Tq * Dq];

// ---------------------------------------------------------------------------
// Kernel A: sequential recurrence, one CTA per batch.
// smem: mem[64*896] fp32 (224KB) + scores/attn[64] + red[160] + bc[16]
// ---------------------------------------------------------------------------
__global__ __launch_bounds__(NTH, 1) void seq_kernel(
    const float* __restrict__ h, const int* __restrict__ mask,
    const float* __restrict__ ln_g, const float* __restrict__ ln_b,
    const float* __restrict__ W_nm, const float* __restrict__ b_nm,
    const float* __restrict__ W_wg, const float* __restrict__ b_wg)
{
    extern __shared__ float smf[];
    float* mem = smf;                 // [Sq*Dq]
    float* sc  = smf + Sq * Dq;       // [64] scores -> attn
    float* red = sc + 64;             // [160] 5 x 32 partials
    float* bc  = red + 160;           // [16] broadcast scalars

    const int tid = threadIdx.x;
    const int w   = tid >> 5;
    const int l   = tid & 31;
    const int b   = blockIdx.x;

    for (int i = tid; i < Sq * Dq; i += NTH) mem[i] = 0.f;

    // persistent per-thread constants (tid < Dq owns dim `tid`)
    float wnm_h = 0.f, wnm_m = 0.f, wwg_h = 0.f, lng = 0.f, lnb = 0.f;
    if (tid < Dq) {
        wnm_h = W_nm[tid];
        wnm_m = W_nm[Dq + tid];
        wwg_h = W_wg[tid];
        lng   = ln_g[tid];
        lnb   = ln_b[tid];
    }
    const float wwg_g = W_wg[Dq];
    const float bnm   = b_nm[0];
    const float bwg   = b_wg[0];

    const float scale = rsqrtf((float)Dq);
    const float* hb = h + (size_t)b * Tq * Dq;
    const int*   mb = mask + (size_t)b * Tq;
    float* mnb = g_mn + (size_t)b * Tq * Dq;

    __syncthreads();

    for (int t = 0; t < Tq; ++t) {
        const float* ht = hb + (size_t)t * Dq;

        // (A) load h_t: lane-pattern float4 regs (d = 4*l + 128*j) + own dim
        float4 hr[7];
        #pragma unroll
        for (int j = 0; j < 7; ++j)
            hr[j] = *(const float4*)(ht + 128 * j + 4 * l);
        float hmine = (tid < Dq) ? ht[tid] : 0.f;
        float pnm = hmine * wnm_h;   // partial h . W_nm[:D]
        float pwg = hmine * wwg_h;   // partial h . W_wg[:D]

        // (B) scores: warp w handles slots 2w, 2w+1 (reads only mem from smem)
        const float4* r0 = (const float4*)(mem + (2 * w) * Dq);
        const float4* r1 = (const float4*)(mem + (2 * w + 1) * Dq);
        float s0 = 0.f, s1 = 0.f;
        #pragma unroll
        for (int j = 0; j < 7; ++j) {
            float4 a = r0[32 * j + l];
            s0 += a.x * hr[j].x + a.y * hr[j].y + a.z * hr[j].z + a.w * hr[j].w;
            float4 c = r1[32 * j + l];
            s1 += c.x * hr[j].x + c.y * hr[j].y + c.z * hr[j].z + c.w * hr[j].w;
        }
        #pragma unroll
        for (int o = 16; o > 0; o >>= 1) {
            s0 += __shfl_xor_sync(0xffffffffu, s0, o);
            s1 += __shfl_xor_sync(0xffffffffu, s1, o);
        }
        if (l == 0) { sc[2 * w] = s0 * scale; sc[2 * w + 1] = s1 * scale; }
        __syncthreads();

        // (D) softmax + argmax over 64 slots, warp 0 only
        // tie-break: lowest index (matches jax.lax.top_k stability)
        if (w == 0) {
            float v0 = sc[l], v1 = sc[l + 32];
            float mx; int mi;
            if (v1 > v0) { mx = v1; mi = l + 32; } else { mx = v0; mi = l; }
            #pragma unroll
            for (int o = 16; o > 0; o >>= 1) {
                float om = __shfl_xor_sync(0xffffffffu, mx, o);
                int   oi = __shfl_xor_sync(0xffffffffu, mi, o);
                if (om > mx || (om == mx && oi < mi)) { mx = om; mi = oi; }
            }
            float e0 = __expf(v0 - mx), e1 = __expf(v1 - mx);
            float es = e0 + e1;
            #pragma unroll
            for (int o = 16; o > 0; o >>= 1)
                es += __shfl_xor_sync(0xffffffffu, es, o);
            float inv = 1.f / es;
            sc[l] = e0 * inv; sc[l + 32] = e1 * inv;
            if (l == 0) bc[0] = __int_as_float(mi);
        }
        __syncthreads();

        // (E) m-pass: thread tid owns dim tid; m = attn . mem[:, tid]
        float mv = 0.f;
        if (tid < Dq) {
            #pragma unroll 8
            for (int s2 = 0; s2 < Sq; ++s2)
                mv += sc[s2] * mem[s2 * Dq + tid];
        }

        // (F) fused 5-way block reduce: sum m, sum m^2, m.Wnm_m, h.Wnm_h, h.Wwg_h
        float p1 = mv, p2 = mv * mv, p3 = mv * wnm_m, p4 = pnm, p5 = pwg;
        #pragma unroll
        for (int o = 16; o > 0; o >>= 1) {
            p1 += __shfl_xor_sync(0xffffffffu, p1, o);
            p2 += __shfl_xor_sync(0xffffffffu, p2, o);
            p3 += __shfl_xor_sync(0xffffffffu, p3, o);
            p4 += __shfl_xor_sync(0xffffffffu, p4, o);
            p5 += __shfl_xor_sync(0xffffffffu, p5, o);
        }
        if (l == 0) {
            red[w] = p1; red[32 + w] = p2; red[64 + w] = p3;
            red[96 + w] = p4; red[128 + w] = p5;
        }
        __syncthreads();

        // (G) final reduce + scalar gate chain
        if (w == 0) {
            float q1 = red[l], q2 = red[32 + l], q3 = red[64 + l];
            float q4 = red[96 + l], q5 = red[128 + l];
            #pragma unroll
            for (int o = 16; o > 0; o >>= 1) {
                q1 += __shfl_xor_sync(0xffffffffu, q1, o);
                q2 += __shfl_xor_sync(0xffffffffu, q2, o);
                q3 += __shfl_xor_sync(0xffffffffu, q3, o);
                q4 += __shfl_xor_sync(0xffffffffu, q4, o);
                q5 += __shfl_xor_sync(0xffffffffu, q5, o);
            }
            if (l == 0) {
                float g  = 1.f / (1.f + expf(-(q4 + q3 + bnm)));
                float wg = 1.f / (1.f + expf(-(q5 + g * wwg_g + bwg)));
                wg = fminf(fmaxf(wg, 0.f), 0.2f) * (float)mb[t];
                float mean = q1 * (1.f / (float)Dq);
                float var  = q2 * (1.f / (float)Dq) - mean * mean;
                float rstd = rsqrtf(var + 1e-5f);
                bc[1] = wg; bc[2] = mean; bc[3] = rstd;
            }
        }
        __syncthreads();

        // (H) LayerNorm(m) -> scratch; top-1 slot write
        {
            float wg = bc[1], mean = bc[2], rstd = bc[3];
            int idx = __float_as_int(bc[0]);
            if (tid < Dq) {
                float mn = (mv - mean) * rstd * lng + lnb;
                mnb[(size_t)t * Dq + tid] = mn;
                float* cell = mem + idx * Dq + tid;
                *cell = *cell * (1.f - wg) + wg * hmine;
            }
        }
        __syncthreads();
    }
}

// ---------------------------------------------------------------------------
// Kernel B: out[m,n] = h[m,n] + clip(0.5 * sum_k mn[m,k] * W_out[n,k], +-2)
// fp32 SIMT 128x128 tiles, 256 threads, 8x8 microtile per thread.
// ---------------------------------------------------------------------------
__global__ __launch_bounds__(256) void gemm_kernel(
    const float* __restrict__ Wt,   // W_out [N,K] row-major
    const float* __restrict__ H,    // h flattened [M,N]
    float* __restrict__ C)          // out [M,N]
{
    __shared__ float As[8][128];
    __shared__ float Bs[8][128];

    const int bm = blockIdx.y * 128;
    const int bn = blockIdx.x * 128;
    const int tid = threadIdx.x;
    const int tr = tid >> 4;          // 0..15
    const int tc = tid & 15;          // 0..15
    const int lr = tid >> 1;          // load row 0..127
    const int lk = (tid & 1) * 4;     // 0 or 4

    const float* Ap = g_mn + (size_t)(bm + lr) * GK + lk;
    const float* Bp = Wt   + (size_t)(bn + lr) * GK + lk;

    float acc[8][8];
    #pragma unroll
    for (int i = 0; i < 8; ++i)
        #pragma unroll
        for (int j = 0; j < 8; ++j) acc[i][j] = 0.f;

    for (int k0 = 0; k0 < GK; k0 += 8) {
        float4 av = *(const float4*)(Ap + k0);
        float4 bv = *(const float4*)(Bp + k0);
        __syncthreads();
        As[lk + 0][lr] = av.x; As[lk + 1][lr] = av.y;
        As[lk + 2][lr] = av.z; As[lk + 3][lr] = av.w;
        Bs[lk + 0][lr] = bv.x; Bs[lk + 1][lr] = bv.y;
        Bs[lk + 2][lr] = bv.z; Bs[lk + 3][lr] = bv.w;
        __syncthreads();
        #pragma unroll
        for (int kk = 0; kk < 8; ++kk) {
            float a[8], bb[8];
            #pragma unroll
            for (int i = 0; i < 8; ++i) a[i]  = As[kk][tr + 16 * i];
            #pragma unroll
            for (int j = 0; j < 8; ++j) bb[j] = Bs[kk][tc + 16 * j];
            #pragma unroll
            for (int i = 0; i < 8; ++i)
                #pragma unroll
                for (int j = 0; j < 8; ++j)
                    acc[i][j] = fmaf(a[i], bb[j], acc[i][j]);
        }
    }

    #pragma unroll
    for (int i = 0; i < 8; ++i) {
        int m = bm + tr + 16 * i;
        #pragma unroll
        for (int j = 0; j < 8; ++j) {
            int n = bn + tc + 16 * j;
            float d2 = fminf(fmaxf(acc[i][j] * 0.5f, -2.f), 2.f);
            C[(size_t)m * GN + n] = H[(size_t)m * GN + n] + d2;
        }
    }
}

// ---------------------------------------------------------------------------
extern "C" void kernel_launch(void* const* d_in, const int* in_sizes, int n_in,
                              void* d_out, int out_size) {
    const float* h    = (const float*)d_in[0];
    const int*   mask = (const int*)  d_in[1];
    const float* lng  = (const float*)d_in[2];
    const float* lnb  = (const float*)d_in[3];
    const float* Wout = (const float*)d_in[4];
    const float* Wnm  = (const float*)d_in[5];
    const float* bnm  = (const float*)d_in[6];
    const float* Wwg  = (const float*)d_in[7];
    const float* bwg  = (const float*)d_in[8];
    float* out = (float*)d_out;

    const size_t smem = (size_t)(Sq * Dq + 64 + 160 + 16) * sizeof(float);
    cudaFuncSetAttribute(seq_kernel,
                         cudaFuncAttributeMaxDynamicSharedMemorySize,
                         (int)smem);

    seq_kernel<<<Bq, NTH, smem>>>(h, mask, lng, lnb, Wnm, bnm, Wwg, bwg);

    dim3 grid(GN / 128, GM / 128);
    gemm_kernel<<<grid, 256>>>(Wout, h, out);
}

// round 3
// speedup vs baseline: 1.5708x; 1.5708x over previous
#include <cuda_runtime.h>
#include <math.h>

#define Bq 8
#define Tq 4096
#define Dq 896
#define Sq 64
#define Cq 128
#define NCq (Tq/Cq)          // 32 chunks

#define GM (Bq*Tq)           // 32768
#define GN Dq
#define GK Dq

// ---------------- global scratch (static allocations) ----------------
__device__ float g_G[Bq][NCq][Cq][Cq];      // h_t . h_j grams per chunk  (67MB)
__device__ float g_hd[Bq][Tq][4];           // h.Wnm_h, h.Wnm_m, h.Wwg_h
__device__ float g_Bb[2][Bq][Sq][Dq];       // memory base, double buffered
__device__ float g_P[Bq][Cq][Sq];           // h_t . B[s] for current chunk
__device__ float g_u[Bq][Sq];               // B[s] . Wnm_m
__device__ float g_beta[Bq][Cq][Sq];        // attn * a
__device__ float g_gamma[Bq][Cq][Cq];       // attn[idx_j] * kappa_j
__device__ float g_afin[Bq][Sq];
__device__ float g_kap[Bq][Cq];
__device__ int   g_idx[Bq][Cq];
__device__ float g_m[(size_t)Bq*Tq*Dq];     // raw m (117MB)
__device__ float g_stats[(size_t)Bq*Tq][2]; // mean, rstd per row

// ---------------------------------------------------------------------
__global__ void init_kernel() {
    int tid = blockIdx.x * blockDim.x + threadIdx.x;
    int nb = Bq * Sq * Dq;                       // 458752
    for (int i = tid; i < nb; i += gridDim.x * blockDim.x)
        (&g_Bb[0][0][0][0])[i] = 0.f;
    int np = Bq * Cq * Sq;                       // 65536
    for (int i = tid; i < np; i += gridDim.x * blockDim.x)
        (&g_P[0][0][0])[i] = 0.f;
    if (tid < Bq * Sq) (&g_u[0][0])[tid] = 0.f;
}

// ---------------------------------------------------------------------
// pre: per (b, chunk) CTA -> G = H_chunk @ H_chunk^T  +  per-row h.w dots
// ---------------------------------------------------------------------
__global__ __launch_bounds__(256) void pre_kernel(
    const float* __restrict__ h,
    const float* __restrict__ W_nm,
    const float* __restrict__ W_wg)
{
    __shared__ float As[8][128];
    const int b = blockIdx.x / NCq;
    const int c = blockIdx.x % NCq;
    const int t0 = c * Cq;
    const int tid = threadIdx.x;
    const int tr = tid >> 4, tc = tid & 15;
    const int lr = tid >> 1, lk = (tid & 1) * 4;

    const float* Hc = h + ((size_t)b * Tq + t0) * Dq;

    float acc[8][8];
    #pragma unroll
    for (int i = 0; i < 8; ++i)
        #pragma unroll
        for (int j = 0; j < 8; ++j) acc[i][j] = 0.f;

    for (int k0 = 0; k0 < Dq; k0 += 8) {
        float4 av = *(const float4*)(Hc + (size_t)lr * Dq + k0 + lk);
        __syncthreads();
        As[lk + 0][lr] = av.x; As[lk + 1][lr] = av.y;
        As[lk + 2][lr] = av.z; As[lk + 3][lr] = av.w;
        __syncthreads();
        #pragma unroll
        for (int kk = 0; kk < 8; ++kk) {
            float a[8], bb[8];
            #pragma unroll
            for (int i = 0; i < 8; ++i) a[i]  = As[kk][tr + 16 * i];
            #pragma unroll
            for (int j = 0; j < 8; ++j) bb[j] = As[kk][tc + 16 * j];
            #pragma unroll
            for (int i = 0; i < 8; ++i)
                #pragma unroll
                for (int j = 0; j < 8; ++j)
                    acc[i][j] = fmaf(a[i], bb[j], acc[i][j]);
        }
    }
    #pragma unroll
    for (int i = 0; i < 8; ++i)
        #pragma unroll
        for (int j = 0; j < 8; ++j)
            g_G[b][c][tr + 16 * i][tc + 16 * j] = acc[i][j];

    // h-dot vectors: 8 warps, 16 rows each
    const int w = tid >> 5, l = tid & 31;
    for (int r = w; r < Cq; r += 8) {
        const float* hr = Hc + (size_t)r * Dq;
        float s0 = 0.f, s1 = 0.f, s2 = 0.f;
        for (int d = l; d < Dq; d += 32) {
            float x = hr[d];
            s0 += x * W_nm[d];
            s1 += x * W_nm[Dq + d];
            s2 += x * W_wg[d];
        }
        #pragma unroll
        for (int o = 16; o > 0; o >>= 1) {
            s0 += __shfl_xor_sync(0xffffffffu, s0, o);
            s1 += __shfl_xor_sync(0xffffffffu, s1, o);
            s2 += __shfl_xor_sync(0xffffffffu, s2, o);
        }
        if (l == 0) {
            g_hd[b][t0 + r][0] = s0;
            g_hd[b][t0 + r][1] = s1;
            g_hd[b][t0 + r][2] = s2;
        }
    }
}

// ---------------------------------------------------------------------
// scan: one warp per batch, 128 scalar recurrence steps for chunk c
// ---------------------------------------------------------------------
__global__ __launch_bounds__(32) void scan_kernel(
    const int* __restrict__ mask,
    const float* __restrict__ b_nm,
    const float* __restrict__ W_wg,
    const float* __restrict__ b_wg,
    int c)
{
    __shared__ float corr[Sq];
    const int b = blockIdx.x;
    const int l = threadIdx.x;
    const int t0 = c * Cq;
    const float scale = rsqrtf((float)Dq);

    float a0 = 1.f, a1 = 1.f;
    float u0 = g_u[b][l], u1 = g_u[b][l + 32];
    float kap0 = 0.f, kap1 = 0.f, kap2 = 0.f, kap3 = 0.f;
    int   id0 = -1, id1 = -1, id2 = -1, id3 = -1;
    float vj[4], hd0[4], hd2[4], mk[4];
    #pragma unroll
    for (int q = 0; q < 4; ++q) {
        int j = l + 32 * q;
        hd0[q] = g_hd[b][t0 + j][0];
        vj[q]  = g_hd[b][t0 + j][1];
        hd2[q] = g_hd[b][t0 + j][2];
        mk[q]  = (float)mask[b * Tq + t0 + j];
    }
    const float wwg_g = W_wg[Dq];
    const float bnm = b_nm[0], bwg = b_wg[0];

    // prefetch t = 0
    float p0 = g_P[b][0][l], p1 = g_P[b][0][l + 32];
    float gr0 = g_G[b][c][0][l],      gr1 = g_G[b][c][0][l + 32];
    float gr2 = g_G[b][c][0][l + 64], gr3 = g_G[b][c][0][l + 96];

    for (int t = 0; t < Cq; ++t) {
        float cp0 = p0, cp1 = p1;
        float cg0 = gr0, cg1 = gr1, cg2 = gr2, cg3 = gr3;
        if (t + 1 < Cq) {                       // prefetch next step
            p0 = g_P[b][t + 1][l]; p1 = g_P[b][t + 1][l + 32];
            gr0 = g_G[b][c][t + 1][l];      gr1 = g_G[b][c][t + 1][l + 32];
            gr2 = g_G[b][c][t + 1][l + 64]; gr3 = g_G[b][c][t + 1][l + 96];
        }

        corr[l] = 0.f; corr[l + 32] = 0.f;
        __syncwarp();
        if (l       < t && id0 >= 0) atomicAdd(&corr[id0], kap0 * cg0);
        if (l + 32  < t && id1 >= 0) atomicAdd(&corr[id1], kap1 * cg1);
        if (l + 64  < t && id2 >= 0) atomicAdd(&corr[id2], kap2 * cg2);
        if (l + 96  < t && id3 >= 0) atomicAdd(&corr[id3], kap3 * cg3);
        __syncwarp();

        float s0 = (a0 * cp0 + corr[l])      * scale;
        float s1 = (a1 * cp1 + corr[l + 32]) * scale;

        // max + argmax (tie -> lowest index)
        float mx; int mi;
        if (s1 > s0) { mx = s1; mi = l + 32; } else { mx = s0; mi = l; }
        #pragma unroll
        for (int o = 16; o > 0; o >>= 1) {
            float om = __shfl_xor_sync(0xffffffffu, mx, o);
            int   oi = __shfl_xor_sync(0xffffffffu, mi, o);
            if (om > mx || (om == mx && oi < mi)) { mx = om; mi = oi; }
        }
        float e0 = __expf(s0 - mx), e1 = __expf(s1 - mx);

        // gather e at stored write-slot indices
        float ei0, ei1, ei2, ei3;
        {
            float ea, eb;
            ea = __shfl_sync(0xffffffffu, e0, id0 & 31);
            eb = __shfl_sync(0xffffffffu, e1, id0 & 31);
            ei0 = (id0 < 32) ? ea : eb;
            ea = __shfl_sync(0xffffffffu, e0, id1 & 31);
            eb = __shfl_sync(0xffffffffu, e1, id1 & 31);
            ei1 = (id1 < 32) ? ea : eb;
            ea = __shfl_sync(0xffffffffu, e0, id2 & 31);
            eb = __shfl_sync(0xffffffffu, e1, id2 & 31);
            ei2 = (id2 < 32) ? ea : eb;
            ea = __shfl_sync(0xffffffffu, e0, id3 & 31);
            eb = __shfl_sync(0xffffffffu, e1, id3 & 31);
            ei3 = (id3 < 32) ? ea : eb;
        }

        float pe = e0 + e1;
        float pd = e0 * a0 * u0 + e1 * a1 * u1;
        float pg = 0.f;
        if (l      < t && id0 >= 0) pg += ei0 * kap0 * vj[0];
        if (l + 32 < t && id1 >= 0) pg += ei1 * kap1 * vj[1];
        if (l + 64 < t && id2 >= 0) pg += ei2 * kap2 * vj[2];
        if (l + 96 < t && id3 >= 0) pg += ei3 * kap3 * vj[3];
        #pragma unroll
        for (int o = 16; o > 0; o >>= 1) {
            pe += __shfl_xor_sync(0xffffffffu, pe, o);
            pd += __shfl_xor_sync(0xffffffffu, pd, o);
            pg += __shfl_xor_sync(0xffffffffu, pg, o);
        }
        float inv = 1.f / pe;
        float mdot = (pd + pg) * inv;

        // per-step scalars (uniform across warp)
        const int qt = t >> 5, rt = t & 31;
        float a_, b_, c_;
        if (qt == 0)      { a_ = hd0[0]; b_ = hd2[0]; c_ = mk[0]; }
        else if (qt == 1) { a_ = hd0[1]; b_ = hd2[1]; c_ = mk[1]; }
        else if (qt == 2) { a_ = hd0[2]; b_ = hd2[2]; c_ = mk[2]; }
        else              { a_ = hd0[3]; b_ = hd2[3]; c_ = mk[3]; }
        float hnm = __shfl_sync(0xffffffffu, a_, rt);
        float hwg = __shfl_sync(0xffffffffu, b_, rt);
        float mkt = __shfl_sync(0xffffffffu, c_, rt);

        float gg = 1.f / (1.f + __expf(-(hnm + mdot + bnm)));
        float wg = 1.f / (1.f + __expf(-(hwg + gg * wwg_g + bwg)));
        wg = fminf(wg, 0.2f) * mkt;

        // record beta / gamma (pre-update state)
        g_beta[b][t][l]      = e0 * inv * a0;
        g_beta[b][t][l + 32] = e1 * inv * a1;
        g_gamma[b][t][l]      = (l      < t && id0 >= 0) ? ei0 * inv * kap0 : 0.f;
        g_gamma[b][t][l + 32] = (l + 32 < t && id1 >= 0) ? ei1 * inv * kap1 : 0.f;
        g_gamma[b][t][l + 64] = (l + 64 < t && id2 >= 0) ? ei2 * inv * kap2 : 0.f;
        g_gamma[b][t][l + 96] = (l + 96 < t && id3 >= 0) ? ei3 * inv * kap3 : 0.f;

        // apply write: decay slot mi, add new coefficient at j = t
        float dec = 1.f - wg;
        if (l      < t && id0 == mi) kap0 *= dec;
        if (l + 32 < t && id1 == mi) kap1 *= dec;
        if (l + 64 < t && id2 == mi) kap2 *= dec;
        if (l + 96 < t && id3 == mi) kap3 *= dec;
        if (mi == l)      a0 *= dec;
        if (mi == l + 32) a1 *= dec;
        if (l == rt) {
            if      (qt == 0) { kap0 = wg; id0 = mi; }
            else if (qt == 1) { kap1 = wg; id1 = mi; }
            else if (qt == 2) { kap2 = wg; id2 = mi; }
            else              { kap3 = wg; id3 = mi; }
        }
    }

    g_afin[b][l] = a0; g_afin[b][l + 32] = a1;
    g_kap[b][l]      = kap0; g_idx[b][l]      = id0;
    g_kap[b][l + 32] = kap1; g_idx[b][l + 32] = id1;
    g_kap[b][l + 64] = kap2; g_idx[b][l + 64] = id2;
    g_kap[b][l + 96] = kap3; g_idx[b][l + 96] = id3;
}

// ---------------------------------------------------------------------
// post: role A (blocks 0..63): B update + next-chunk P,u
//       role B (blocks 64..119): m = beta@B_old + gamma@H -> g_m
// ---------------------------------------------------------------------
__global__ __launch_bounds__(256) void post_kernel(
    const float* __restrict__ h,
    const float* __restrict__ W_nm,
    int c)
{
    __shared__ int   s_idx[Cq];
    __shared__ float s_kap[Cq];
    __shared__ int   s_cnt[8];
    __shared__ int   s_list[8][Cq];
    __shared__ float s_u[8];
    __shared__ float As2[8][128];
    __shared__ float Bs[8][128];

    const int tid = threadIdx.x;
    const int cur = c & 1;

    if (blockIdx.x < 64) {
        // ----------------- role A -----------------
        if (c == NCq - 1) return;   // no next chunk
        const int b = blockIdx.x >> 3;
        const int sg = blockIdx.x & 7;
        const int s0 = sg * 8;
        const int t0 = c * Cq;

        if (tid < Cq) { s_idx[tid] = g_idx[b][tid]; s_kap[tid] = g_kap[b][tid]; }
        if (tid < 8)  { s_cnt[tid] = 0; s_u[tid] = 0.f; }
        __syncthreads();
        if (tid == 0) {   // deterministic list build
            for (int j = 0; j < Cq; ++j) {
                int s = s_idx[j];
                if (s >= s0 && s < s0 + 8) s_list[s - s0][s_cnt[s - s0]++] = j;
            }
        }
        __syncthreads();

        const float* Bold = &g_Bb[cur][b][0][0];
        float*       Bnew = &g_Bb[cur ^ 1][b][0][0];
        const float* Hc = h + ((size_t)b * Tq + t0) * Dq;

        for (int so = 0; so < 8; ++so) {
            int s = s0 + so;
            float as = g_afin[b][s];
            int nj = s_cnt[so];
            float pu = 0.f;
            for (int d = tid; d < Dq; d += 256) {
                float acc = as * Bold[(size_t)s * Dq + d];
                for (int k = 0; k < nj; ++k) {
                    int j = s_list[so][k];
                    acc = fmaf(s_kap[j], Hc[(size_t)j * Dq + d], acc);
                }
                Bnew[(size_t)s * Dq + d] = acc;
                pu = fmaf(acc, W_nm[Dq + d], pu);
            }
            #pragma unroll
            for (int o = 16; o > 0; o >>= 1)
                pu += __shfl_xor_sync(0xffffffffu, pu, o);
            if ((tid & 31) == 0) atomicAdd(&s_u[so], pu);
        }
        __syncthreads();
        if (tid < 8) g_u[b][s0 + tid] = s_u[tid];

        // P for next chunk
        const float* Hn = h + ((size_t)b * Tq + (c + 1) * Cq) * Dq;
        #pragma unroll
        for (int rep = 0; rep < 4; ++rep) {
            int oid = tid + 256 * rep;           // 0..1023
            int t = oid >> 3, so = oid & 7;
            const float4* hp = (const float4*)(Hn + (size_t)t * Dq);
            const float4* bp = (const float4*)(Bnew + (size_t)(s0 + so) * Dq);
            float acc = 0.f;
            #pragma unroll 4
            for (int d4 = 0; d4 < Dq / 4; ++d4) {
                float4 x = hp[d4], y = bp[d4];
                acc += x.x * y.x + x.y * y.y + x.z * y.z + x.w * y.w;
            }
            g_P[b][t][s0 + so] = acc;
        }
    } else {
        // ----------------- role B: m build -----------------
        const int bi = blockIdx.x - 64;
        const int b = bi / 7;
        const int n0 = (bi % 7) * 128;
        const int t0 = c * Cq;
        const float* Bold = &g_Bb[cur][b][0][0];
        const float* Hc = h + ((size_t)b * Tq + t0) * Dq;

        const int tr = tid >> 4, tc = tid & 15;
        const int lr = tid >> 1, lk = (tid & 1) * 4;
        const int kr = tid >> 5, nc = (tid & 31) * 4;

        float acc[8][8];
        #pragma unroll
        for (int i = 0; i < 8; ++i)
            #pragma unroll
            for (int j = 0; j < 8; ++j) acc[i][j] = 0.f;

        for (int k0 = 0; k0 < Sq + Cq; k0 += 8) {
            float4 av = (k0 < Sq)
                ? *(const float4*)(&g_beta[b][lr][k0 + lk])
                : *(const float4*)(&g_gamma[b][lr][k0 - Sq + lk]);
            int kg = k0 + kr;
            const float* rp = (kg < Sq) ? (Bold + (size_t)kg * Dq)
                                        : (Hc + (size_t)(kg - Sq) * Dq);
            float4 bv = *(const float4*)(rp + n0 + nc);
            __syncthreads();
            As2[lk + 0][lr] = av.x; As2[lk + 1][lr] = av.y;
            As2[lk + 2][lr] = av.z; As2[lk + 3][lr] = av.w;
            Bs[kr][nc + 0] = bv.x; Bs[kr][nc + 1] = bv.y;
            Bs[kr][nc + 2] = bv.z; Bs[kr][nc + 3] = bv.w;
            __syncthreads();
            #pragma unroll
            for (int kk = 0; kk < 8; ++kk) {
                float a[8], bb[8];
                #pragma unroll
                for (int i = 0; i < 8; ++i) a[i]  = As2[kk][tr + 16 * i];
                #pragma unroll
                for (int j = 0; j < 8; ++j) bb[j] = Bs[kk][tc + 16 * j];
                #pragma unroll
                for (int i = 0; i < 8; ++i)
                    #pragma unroll
                    for (int j = 0; j < 8; ++j)
                        acc[i][j] = fmaf(a[i], bb[j], acc[i][j]);
            }
        }
        #pragma unroll
        for (int i = 0; i < 8; ++i) {
            size_t row = (size_t)b * Tq + t0 + tr + 16 * i;
            #pragma unroll
            for (int j = 0; j < 8; ++j)
                g_m[row * Dq + n0 + tc + 16 * j] = acc[i][j];
        }
    }
}

// ---------------------------------------------------------------------
__global__ __launch_bounds__(256) void stats_kernel() {
    int row = blockIdx.x * 8 + (threadIdx.x >> 5);
    int l = threadIdx.x & 31;
    const float* mr = g_m + (size_t)row * Dq;
    float s = 0.f, s2 = 0.f;
    for (int d = l; d < Dq; d += 32) { float v = mr[d]; s += v; s2 += v * v; }
    #pragma unroll
    for (int o = 16; o > 0; o >>= 1) {
        s  += __shfl_xor_sync(0xffffffffu, s, o);
        s2 += __shfl_xor_sync(0xffffffffu, s2, o);
    }
    if (l == 0) {
        float mu = s * (1.f / (float)Dq);
        float var = s2 * (1.f / (float)Dq) - mu * mu;
        g_stats[row][0] = mu;
        g_stats[row][1] = rsqrtf(var + 1e-5f);
    }
}

// ---------------------------------------------------------------------
// final: out = h + clip(0.5 * LN(m) @ W_out^T, +-2), LN fused into A load
// ---------------------------------------------------------------------
__global__ __launch_bounds__(256) void gemm_kernel(
    const float* __restrict__ Wt,
    const float* __restrict__ H,
    const float* __restrict__ lng,
    const float* __restrict__ lnb,
    float* __restrict__ C)
{
    __shared__ float As[8][128];
    __shared__ float Bs[8][128];

    const int bm = blockIdx.y * 128;
    const int bn = blockIdx.x * 128;
    const int tid = threadIdx.x;
    const int tr = tid >> 4, tc = tid & 15;
    const int lr = tid >> 1, lk = (tid & 1) * 4;

    const float* Ap = g_m + (size_t)(bm + lr) * GK + lk;
    const float* Bp = Wt  + (size_t)(bn + lr) * GK + lk;
    const float mu = g_stats[bm + lr][0];
    const float rs = g_stats[bm + lr][1];

    float acc[8][8];
    #pragma unroll
    for (int i = 0; i < 8; ++i)
        #pragma unroll
        for (int j = 0; j < 8; ++j) acc[i][j] = 0.f;

    for (int k0 = 0; k0 < GK; k0 += 8) {
        float4 av = *(const float4*)(Ap + k0);
        float4 bv = *(const float4*)(Bp + k0);
        float4 gv = *(const float4*)(lng + k0 + lk);
        float4 ov = *(const float4*)(lnb + k0 + lk);
        av.x = (av.x - mu) * rs * gv.x + ov.x;
        av.y = (av.y - mu) * rs * gv.y + ov.y;
        av.z = (av.z - mu) * rs * gv.z + ov.z;
        av.w = (av.w - mu) * rs * gv.w + ov.w;
        __syncthreads();
        As[lk + 0][lr] = av.x; As[lk + 1][lr] = av.y;
        As[lk + 2][lr] = av.z; As[lk + 3][lr] = av.w;
        Bs[lk + 0][lr] = bv.x; Bs[lk + 1][lr] = bv.y;
        Bs[lk + 2][lr] = bv.z; Bs[lk + 3][lr] = bv.w;
        __syncthreads();
        #pragma unroll
        for (int kk = 0; kk < 8; ++kk) {
            float a[8], bb[8];
            #pragma unroll
            for (int i = 0; i < 8; ++i) a[i]  = As[kk][tr + 16 * i];
            #pragma unroll
            for (int j = 0; j < 8; ++j) bb[j] = Bs[kk][tc + 16 * j];
            #pragma unroll
            for (int i = 0; i < 8; ++i)
                #pragma unroll
                for (int j = 0; j < 8; ++j)
                    acc[i][j] = fmaf(a[i], bb[j], acc[i][j]);
        }
    }

    #pragma unroll
    for (int i = 0; i < 8; ++i) {
        int m = bm + tr + 16 * i;
        #pragma unroll
        for (int j = 0; j < 8; ++j) {
            int n = bn + tc + 16 * j;
            float d2 = fminf(fmaxf(acc[i][j] * 0.5f, -2.f), 2.f);
            C[(size_t)m * GN + n] = H[(size_t)m * GN + n] + d2;
        }
    }
}

// ---------------------------------------------------------------------
extern "C" void kernel_launch(void* const* d_in, const int* in_sizes, int n_in,
                              void* d_out, int out_size) {
    const float* h    = (const float*)d_in[0];
    const int*   mask = (const int*)  d_in[1];
    const float* lng  = (const float*)d_in[2];
    const float* lnb  = (const float*)d_in[3];
    const float* Wout = (const float*)d_in[4];
    const float* Wnm  = (const float*)d_in[5];
    const float* bnm  = (const float*)d_in[6];
    const float* Wwg  = (const float*)d_in[7];
    const float* bwg  = (const float*)d_in[8];
    float* out = (float*)d_out;

    init_kernel<<<256, 256>>>();
    pre_kernel<<<Bq * NCq, 256>>>(h, Wnm, Wwg);

    for (int c = 0; c < NCq; ++c) {
        scan_kernel<<<Bq, 32>>>(mask, bnm, Wwg, bwg, c);
        post_kernel<<<120, 256>>>(h, Wnm, c);
    }

    stats_kernel<<<GM / 8, 256>>>();

    dim3 grid(GN / 128, GM / 128);
    gemm_kernel<<<grid, 256>>>(Wout, h, lng, lnb, out);
}

// round 4
// speedup vs baseline: 2.1741x; 1.3840x over previous
#include <cuda_runtime.h>
#include <math.h>

#define Bq 8
#define Tq 4096
#define Dq 896
#define Sq 64
#define Cq 128
#define NCq 32

#define GM (Bq*Tq)
#define GN Dq
#define GK Dq

// ---------------- global scratch ----------------
__device__ float g_G[Bq][NCq][Cq][Cq];        // self grams (67MB)
__device__ float g_hd[Bq][Tq][4];             // h.Wnm_h, h.Wnm_m, h.Wwg_h
__device__ float g_Ball[NCq][Bq][Sq][Dq];     // memory base at start of each chunk (59MB)
__device__ float g_P[Bq][Cq][Sq];             // h_t . B[s] for current chunk
__device__ float g_u[Bq][Sq];                 // B[s] . Wnm_m
__device__ float g_beta[Bq][NCq][Cq][Sq];     // attn*a per chunk (34MB)
__device__ float g_gamma[Bq][NCq][Cq][Cq];    // attn[idx]*kappa per chunk (67MB)
__device__ float g_afin[Bq][Sq];
__device__ float g_kap[Bq][Cq];
__device__ int   g_idx[Bq][Cq];
__device__ int   g_fscan[Bq];
__device__ float g_m[(size_t)Bq*Tq*Dq];       // raw m (117MB)
__device__ float g_stats[(size_t)Bq*Tq][2];

// smem layout for chunk_kernel (float offsets)
#define OF_G    0        // 16384
#define OF_P    16384    // 8192
#define OF_HD   24576    // 512 (float4[128])
#define OF_KAP  25088    // 128
#define OF_IDX  25216    // 128 (int)
#define OF_AF   25344    // 64
#define OF_U    25408    // 64
#define OF_CORR 25472    // 64
#define SMEM_FLOATS 25536
#define SMEM_BYTES (SMEM_FLOATS*4)

__device__ __forceinline__ unsigned okey(float f) {
    unsigned u = __float_as_uint(f);
    return (u & 0x80000000u) ? ~u : (u | 0x80000000u);
}
__device__ __forceinline__ float dekey(unsigned k) {
    unsigned u = (k & 0x80000000u) ? (k ^ 0x80000000u) : ~k;
    return __uint_as_float(u);
}

// ---------------------------------------------------------------------
__global__ void init_kernel() {
    int tid = blockIdx.x * blockDim.x + threadIdx.x;
    int stride = gridDim.x * blockDim.x;
    int nb = Bq * Sq * Dq;                       // Ball[0]
    for (int i = tid; i < nb; i += stride) (&g_Ball[0][0][0][0])[i] = 0.f;
    int np = Bq * Cq * Sq;
    for (int i = tid; i < np; i += stride) (&g_P[0][0][0])[i] = 0.f;
    if (tid < Bq * Sq) (&g_u[0][0])[tid] = 0.f;
    if (tid < Bq) g_fscan[tid] = 0;
}

// ---------------------------------------------------------------------
// pre: per (b, chunk) CTA -> G = H_chunk @ H_chunk^T  +  per-row h.w dots
// ---------------------------------------------------------------------
__global__ __launch_bounds__(256) void pre_kernel(
    const float* __restrict__ h,
    const float* __restrict__ W_nm,
    const float* __restrict__ W_wg)
{
    __shared__ float As[8][128];
    const int b = blockIdx.x / NCq;
    const int c = blockIdx.x % NCq;
    const int t0 = c * Cq;
    const int tid = threadIdx.x;
    const int tr = tid >> 4, tc = tid & 15;
    const int lr = tid >> 1, lk = (tid & 1) * 4;

    const float* Hc = h + ((size_t)b * Tq + t0) * Dq;

    float acc[8][8];
    #pragma unroll
    for (int i = 0; i < 8; ++i)
        #pragma unroll
        for (int j = 0; j < 8; ++j) acc[i][j] = 0.f;

    float4 av = *(const float4*)(Hc + (size_t)lr * Dq + lk);
    for (int k0 = 0; k0 < Dq; k0 += 8) {
        __syncthreads();
        As[lk + 0][lr] = av.x; As[lk + 1][lr] = av.y;
        As[lk + 2][lr] = av.z; As[lk + 3][lr] = av.w;
        __syncthreads();
        if (k0 + 8 < Dq)
            av = *(const float4*)(Hc + (size_t)lr * Dq + k0 + 8 + lk);
        #pragma unroll
        for (int kk = 0; kk < 8; ++kk) {
            float a[8], bb[8];
            #pragma unroll
            for (int i = 0; i < 8; ++i) a[i]  = As[kk][tr + 16 * i];
            #pragma unroll
            for (int j = 0; j < 8; ++j) bb[j] = As[kk][tc + 16 * j];
            #pragma unroll
            for (int i = 0; i < 8; ++i)
                #pragma unroll
                for (int j = 0; j < 8; ++j)
                    acc[i][j] = fmaf(a[i], bb[j], acc[i][j]);
        }
    }
    #pragma unroll
    for (int i = 0; i < 8; ++i)
        #pragma unroll
        for (int j = 0; j < 8; ++j)
            g_G[b][c][tr + 16 * i][tc + 16 * j] = acc[i][j];

    const int w = tid >> 5, l = tid & 31;
    for (int r = w; r < Cq; r += 8) {
        const float* hr = Hc + (size_t)r * Dq;
        float s0 = 0.f, s1 = 0.f, s2 = 0.f;
        for (int d = l; d < Dq; d += 32) {
            float x = hr[d];
            s0 += x * W_nm[d];
            s1 += x * W_nm[Dq + d];
            s2 += x * W_wg[d];
        }
        #pragma unroll
        for (int o = 16; o > 0; o >>= 1) {
            s0 += __shfl_xor_sync(0xffffffffu, s0, o);
            s1 += __shfl_xor_sync(0xffffffffu, s1, o);
            s2 += __shfl_xor_sync(0xffffffffu, s2, o);
        }
        if (l == 0) {
            g_hd[b][t0 + r][0] = s0;
            g_hd[b][t0 + r][1] = s1;
            g_hd[b][t0 + r][2] = s2;
        }
    }
}

// ---------------------------------------------------------------------
// chunk: blocks 0..7 scan (warp0) from smem; blocks 8..71 spin then
//        B-update + P for next chunk. All blocks co-resident (72 <= 148).
// ---------------------------------------------------------------------
__global__ __launch_bounds__(256) void chunk_kernel(
    const float* __restrict__ h, const int* __restrict__ mask,
    const float* __restrict__ b_nm, const float* __restrict__ W_wg,
    const float* __restrict__ b_wg, int c)
{
    extern __shared__ float sm[];
    float*  sG   = sm + OF_G;
    float*  sP   = sm + OF_P;
    float4* sHd  = (float4*)(sm + OF_HD);
    float*  sKap = sm + OF_KAP;
    int*    sIdx = (int*)(sm + OF_IDX);
    float*  sAf  = sm + OF_AF;
    float*  sU   = sm + OF_U;
    float*  corr = sm + OF_CORR;
    const int tid = threadIdx.x;

    if (blockIdx.x < 8) {
        const int b = blockIdx.x;
        const int t0 = c * Cq;
        // stage everything the scan touches into smem
        const float4* gsrc = (const float4*)&g_G[b][c][0][0];
        for (int i = tid; i < Cq * Cq / 4; i += 256) ((float4*)sG)[i] = gsrc[i];
        const float4* psrc = (const float4*)&g_P[b][0][0];
        for (int i = tid; i < Cq * Sq / 4; i += 256) ((float4*)sP)[i] = psrc[i];
        if (tid < Cq)
            sHd[tid] = make_float4(g_hd[b][t0 + tid][0], g_hd[b][t0 + tid][1],
                                   g_hd[b][t0 + tid][2],
                                   (float)mask[b * Tq + t0 + tid]);
        if (tid < Sq) sU[tid] = g_u[b][tid];
        __syncthreads();
        if (tid >= 32) return;

        const int l = tid;
        const float scale = rsqrtf((float)Dq);
        float a0 = 1.f, a1 = 1.f;
        float u0 = sU[l], u1 = sU[l + 32];
        float kap0 = 0.f, kap1 = 0.f, kap2 = 0.f, kap3 = 0.f;
        int id0 = -1, id1 = -1, id2 = -1, id3 = -1;
        const float vj0 = sHd[l].y, vj1 = sHd[l + 32].y;
        const float vj2 = sHd[l + 64].y, vj3 = sHd[l + 96].y;
        const float wwg_g = W_wg[Dq];
        const float bnm = b_nm[0], bwg = b_wg[0];
        float* bet = &g_beta[b][c][0][0];
        float* gam = &g_gamma[b][c][0][0];

        for (int t = 0; t < Cq; ++t) {
            float cp0 = sP[t * Sq + l],      cp1 = sP[t * Sq + l + 32];
            float cg0 = sG[t * Cq + l],      cg1 = sG[t * Cq + l + 32];
            float cg2 = sG[t * Cq + l + 64], cg3 = sG[t * Cq + l + 96];

            corr[l] = 0.f; corr[l + 32] = 0.f;
            __syncwarp();
            if (l      < t && id0 >= 0) atomicAdd(&corr[id0], kap0 * cg0);
            if (l + 32 < t && id1 >= 0) atomicAdd(&corr[id1], kap1 * cg1);
            if (l + 64 < t && id2 >= 0) atomicAdd(&corr[id2], kap2 * cg2);
            if (l + 96 < t && id3 >= 0) atomicAdd(&corr[id3], kap3 * cg3);
            __syncwarp();

            float s0 = (a0 * cp0 + corr[l])      * scale;
            float s1 = (a1 * cp1 + corr[l + 32]) * scale;

            unsigned k0 = okey(s0), k1 = okey(s1);
            unsigned kmx = __reduce_max_sync(0xffffffffu, k0 > k1 ? k0 : k1);
            float mx = dekey(kmx);
            unsigned cand = (k0 == kmx) ? (unsigned)l : 1000u;
            if (k1 == kmx && (unsigned)(l + 32) < cand) cand = (unsigned)(l + 32);
            int mi = (int)__reduce_min_sync(0xffffffffu, cand);

            float e0 = __expf(s0 - mx), e1 = __expf(s1 - mx);

            float ei0, ei1, ei2, ei3;
            {
                float ea, eb;
                ea = __shfl_sync(0xffffffffu, e0, id0 & 31);
                eb = __shfl_sync(0xffffffffu, e1, id0 & 31);
                ei0 = (id0 < 32) ? ea : eb;
                ea = __shfl_sync(0xffffffffu, e0, id1 & 31);
                eb = __shfl_sync(0xffffffffu, e1, id1 & 31);
                ei1 = (id1 < 32) ? ea : eb;
                ea = __shfl_sync(0xffffffffu, e0, id2 & 31);
                eb = __shfl_sync(0xffffffffu, e1, id2 & 31);
                ei2 = (id2 < 32) ? ea : eb;
                ea = __shfl_sync(0xffffffffu, e0, id3 & 31);
                eb = __shfl_sync(0xffffffffu, e1, id3 & 31);
                ei3 = (id3 < 32) ? ea : eb;
            }

            float pe = e0 + e1;
            float pd = e0 * a0 * u0 + e1 * a1 * u1;
            float pg = 0.f;
            if (l      < t && id0 >= 0) pg += ei0 * kap0 * vj0;
            if (l + 32 < t && id1 >= 0) pg += ei1 * kap1 * vj1;
            if (l + 64 < t && id2 >= 0) pg += ei2 * kap2 * vj2;
            if (l + 96 < t && id3 >= 0) pg += ei3 * kap3 * vj3;
            #pragma unroll
            for (int o = 16; o > 0; o >>= 1) {
                pe += __shfl_xor_sync(0xffffffffu, pe, o);
                pd += __shfl_xor_sync(0xffffffffu, pd, o);
                pg += __shfl_xor_sync(0xffffffffu, pg, o);
            }
            float inv = 1.f / pe;
            float mdot = (pd + pg) * inv;

            float4 hdt = sHd[t];
            float gg = 1.f / (1.f + __expf(-(hdt.x + mdot + bnm)));
            float wg = 1.f / (1.f + __expf(-(hdt.z + gg * wwg_g + bwg)));
            wg = fminf(wg, 0.2f) * hdt.w;

            bet[t * Sq + l]      = e0 * inv * a0;
            bet[t * Sq + l + 32] = e1 * inv * a1;
            gam[t * Cq + l]      = (l      < t && id0 >= 0) ? ei0 * inv * kap0 : 0.f;
            gam[t * Cq + l + 32] = (l + 32 < t && id1 >= 0) ? ei1 * inv * kap1 : 0.f;
            gam[t * Cq + l + 64] = (l + 64 < t && id2 >= 0) ? ei2 * inv * kap2 : 0.f;
            gam[t * Cq + l + 96] = (l + 96 < t && id3 >= 0) ? ei3 * inv * kap3 : 0.f;

            float dec = 1.f - wg;
            if (l      < t && id0 == mi) kap0 *= dec;
            if (l + 32 < t && id1 == mi) kap1 *= dec;
            if (l + 64 < t && id2 == mi) kap2 *= dec;
            if (l + 96 < t && id3 == mi) kap3 *= dec;
            if (mi == l)      a0 *= dec;
            if (mi == l + 32) a1 *= dec;
            const int qt = t >> 5, rt = t & 31;
            if (l == rt) {
                if      (qt == 0) { kap0 = wg; id0 = mi; }
                else if (qt == 1) { kap1 = wg; id1 = mi; }
                else if (qt == 2) { kap2 = wg; id2 = mi; }
                else              { kap3 = wg; id3 = mi; }
            }
        }

        // epilogue: publish kap/idx/afin, update u scalars
        sKap[l] = kap0; sKap[l + 32] = kap1; sKap[l + 64] = kap2; sKap[l + 96] = kap3;
        sIdx[l] = id0;  sIdx[l + 32] = id1;  sIdx[l + 64] = id2;  sIdx[l + 96] = id3;
        __syncwarp();
        float un0 = a0 * u0, un1 = a1 * u1;
        for (int j = 0; j < Cq; ++j) {
            int s = sIdx[j]; float kj = sKap[j]; float hj = sHd[j].y;
            if (s == l)      un0 += kj * hj;
            if (s == l + 32) un1 += kj * hj;
        }
        g_u[b][l] = un0; g_u[b][l + 32] = un1;
        g_kap[b][l] = kap0; g_kap[b][l + 32] = kap1;
        g_kap[b][l + 64] = kap2; g_kap[b][l + 96] = kap3;
        g_idx[b][l] = id0; g_idx[b][l + 32] = id1;
        g_idx[b][l + 64] = id2; g_idx[b][l + 96] = id3;
        g_afin[b][l] = a0; g_afin[b][l + 32] = a1;
        __threadfence();
        if (l == 0) atomicExch(&g_fscan[b], c + 1);
    } else {
        // -------- B-update + P for next chunk --------
        if (c == NCq - 1) return;
        const int id = blockIdx.x - 8;
        const int b = id >> 3, s0 = (id & 7) * 8;

        if (tid == 0) {
            volatile int* fs = (volatile int*)&g_fscan[0];
            while (fs[b] < c + 1) {}
            __threadfence();
        }
        __syncthreads();
        if (tid < Cq) { sKap[tid] = g_kap[b][tid]; sIdx[tid] = g_idx[b][tid]; }
        if (tid < 8) sAf[tid] = g_afin[b][s0 + tid];
        __syncthreads();

        const int w = tid >> 5, l = tid & 31;
        const float* Hc = h + ((size_t)b * Tq + c * Cq) * Dq;

        {   // B-update: warp w owns slot s0+w
            const int s = s0 + w;
            const float4* Bo = (const float4*)&g_Ball[c][b][s][0];
            float4*       Bn = (float4*)&g_Ball[c + 1][b][s][0];
            const float as = sAf[w];
            float4 acc[7];
            #pragma unroll
            for (int q = 0; q < 7; ++q) {
                float4 v = Bo[q * 32 + l];
                acc[q] = make_float4(as * v.x, as * v.y, as * v.z, as * v.w);
            }
            for (int j = 0; j < Cq; ++j) {
                if (sIdx[j] == s) {
                    float kj = sKap[j];
                    const float4* hjp = (const float4*)(Hc + (size_t)j * Dq);
                    #pragma unroll
                    for (int q = 0; q < 7; ++q) {
                        float4 hv = hjp[q * 32 + l];
                        acc[q].x += kj * hv.x; acc[q].y += kj * hv.y;
                        acc[q].z += kj * hv.z; acc[q].w += kj * hv.w;
                    }
                }
            }
            #pragma unroll
            for (int q = 0; q < 7; ++q) Bn[q * 32 + l] = acc[q];
        }
        __syncthreads();   // Bnew globally visible within block

        // P[t][s] = Hn[t] . Bnew[s], thread -> (t, 4 slots)
        const int t = tid >> 1, sh = (tid & 1) * 4;
        const float4* Hn = (const float4*)(h + ((size_t)b * Tq + (c + 1) * Cq + t) * Dq);
        const float4* B0 = (const float4*)&g_Ball[c + 1][b][s0 + sh + 0][0];
        const float4* B1 = (const float4*)&g_Ball[c + 1][b][s0 + sh + 1][0];
        const float4* B2 = (const float4*)&g_Ball[c + 1][b][s0 + sh + 2][0];
        const float4* B3 = (const float4*)&g_Ball[c + 1][b][s0 + sh + 3][0];
        float a0 = 0.f, a1 = 0.f, a2 = 0.f, a3 = 0.f;
        #pragma unroll 4
        for (int k = 0; k < Dq / 4; ++k) {
            float4 hv = Hn[k];
            float4 x;
            x = B0[k]; a0 += hv.x * x.x + hv.y * x.y + hv.z * x.z + hv.w * x.w;
            x = B1[k]; a1 += hv.x * x.x + hv.y * x.y + hv.z * x.z + hv.w * x.w;
            x = B2[k]; a2 += hv.x * x.x + hv.y * x.y + hv.z * x.z + hv.w * x.w;
            x = B3[k]; a3 += hv.x * x.x + hv.y * x.y + hv.z * x.z + hv.w * x.w;
        }
        g_P[b][t][s0 + sh + 0] = a0;
        g_P[b][t][s0 + sh + 1] = a1;
        g_P[b][t][s0 + sh + 2] = a2;
        g_P[b][t][s0 + sh + 3] = a3;
    }
}

// ---------------------------------------------------------------------
// m-build over ALL chunks at once: m = [beta|gamma] @ [B_c ; H_c]
// ---------------------------------------------------------------------
__global__ __launch_bounds__(256) void mbuild_kernel(const float* __restrict__ h)
{
    __shared__ float As2[8][128];
    __shared__ float Bs[8][128];

    const int cc = blockIdx.x / 56;
    const int r  = blockIdx.x % 56;
    const int b  = r / 7;
    const int n0 = (r % 7) * 128;
    const int t0 = cc * Cq;
    const int tid = threadIdx.x;

    const float* Bold = &g_Ball[cc][b][0][0];
    const float* Hc = h + ((size_t)b * Tq + t0) * Dq;
    const float* bet = &g_beta[b][cc][0][0];
    const float* gam = &g_gamma[b][cc][0][0];

    const int tr = tid >> 4, tc = tid & 15;
    const int lr = tid >> 1, lk = (tid & 1) * 4;
    const int kr = tid >> 5, nc = (tid & 31) * 4;

    float acc[8][8];
    #pragma unroll
    for (int i = 0; i < 8; ++i)
        #pragma unroll
        for (int j = 0; j < 8; ++j) acc[i][j] = 0.f;

    for (int k0 = 0; k0 < Sq + Cq; k0 += 8) {
        float4 av = (k0 < Sq)
            ? *(const float4*)(bet + lr * Sq + k0 + lk)
            : *(const float4*)(gam + lr * Cq + k0 - Sq + lk);
        int kg = k0 + kr;
        const float* rp = (kg < Sq) ? (Bold + (size_t)kg * Dq)
                                    : (Hc + (size_t)(kg - Sq) * Dq);
        float4 bv = *(const float4*)(rp + n0 + nc);
        __syncthreads();
        As2[lk + 0][lr] = av.x; As2[lk + 1][lr] = av.y;
        As2[lk + 2][lr] = av.z; As2[lk + 3][lr] = av.w;
        Bs[kr][nc + 0] = bv.x; Bs[kr][nc + 1] = bv.y;
        Bs[kr][nc + 2] = bv.z; Bs[kr][nc + 3] = bv.w;
        __syncthreads();
        #pragma unroll
        for (int kk = 0; kk < 8; ++kk) {
            float a[8], bb[8];
            #pragma unroll
            for (int i = 0; i < 8; ++i) a[i]  = As2[kk][tr + 16 * i];
            #pragma unroll
            for (int j = 0; j < 8; ++j) bb[j] = Bs[kk][tc + 16 * j];
            #pragma unroll
            for (int i = 0; i < 8; ++i)
                #pragma unroll
                for (int j = 0; j < 8; ++j)
                    acc[i][j] = fmaf(a[i], bb[j], acc[i][j]);
        }
    }
    #pragma unroll
    for (int i = 0; i < 8; ++i) {
        size_t row = (size_t)b * Tq + t0 + tr + 16 * i;
        #pragma unroll
        for (int j = 0; j < 8; ++j)
            g_m[row * Dq + n0 + tc + 16 * j] = acc[i][j];
    }
}

// ---------------------------------------------------------------------
__global__ __launch_bounds__(256) void stats_kernel() {
    int row = blockIdx.x * 8 + (threadIdx.x >> 5);
    int l = threadIdx.x & 31;
    const float* mr = g_m + (size_t)row * Dq;
    float s = 0.f, s2 = 0.f;
    for (int d = l; d < Dq; d += 32) { float v = mr[d]; s += v; s2 += v * v; }
    #pragma unroll
    for (int o = 16; o > 0; o >>= 1) {
        s  += __shfl_xor_sync(0xffffffffu, s, o);
        s2 += __shfl_xor_sync(0xffffffffu, s2, o);
    }
    if (l == 0) {
        float mu = s * (1.f / (float)Dq);
        float var = s2 * (1.f / (float)Dq) - mu * mu;
        g_stats[row][0] = mu;
        g_stats[row][1] = rsqrtf(var + 1e-5f);
    }
}

// ---------------------------------------------------------------------
// final: out = h + clip(0.5 * LN(m) @ W_out^T, +-2), LN fused into A load
// ---------------------------------------------------------------------
__global__ __launch_bounds__(256) void gemm_kernel(
    const float* __restrict__ Wt,
    const float* __restrict__ H,
    const float* __restrict__ lng,
    const float* __restrict__ lnb,
    float* __restrict__ C)
{
    __shared__ float As[8][128];
    __shared__ float Bs[8][128];

    const int bm = blockIdx.y * 128;
    const int bn = blockIdx.x * 128;
    const int tid = threadIdx.x;
    const int tr = tid >> 4, tc = tid & 15;
    const int lr = tid >> 1, lk = (tid & 1) * 4;

    const float* Ap = g_m + (size_t)(bm + lr) * GK + lk;
    const float* Bp = Wt  + (size_t)(bn + lr) * GK + lk;
    const float mu = g_stats[bm + lr][0];
    const float rs = g_stats[bm + lr][1];

    float acc[8][8];
    #pragma unroll
    for (int i = 0; i < 8; ++i)
        #pragma unroll
        for (int j = 0; j < 8; ++j) acc[i][j] = 0.f;

    float4 av = *(const float4*)(Ap);
    float4 bv = *(const float4*)(Bp);

    for (int k0 = 0; k0 < GK; k0 += 8) {
        float4 gv = *(const float4*)(lng + k0 + lk);
        float4 ov = *(const float4*)(lnb + k0 + lk);
        float4 an;
        an.x = (av.x - mu) * rs * gv.x + ov.x;
        an.y = (av.y - mu) * rs * gv.y + ov.y;
        an.z = (av.z - mu) * rs * gv.z + ov.z;
        an.w = (av.w - mu) * rs * gv.w + ov.w;
        __syncthreads();
        As[lk + 0][lr] = an.x; As[lk + 1][lr] = an.y;
        As[lk + 2][lr] = an.z; As[lk + 3][lr] = an.w;
        Bs[lk + 0][lr] = bv.x; Bs[lk + 1][lr] = bv.y;
        Bs[lk + 2][lr] = bv.z; Bs[lk + 3][lr] = bv.w;
        __syncthreads();
        if (k0 + 8 < GK) {
            av = *(const float4*)(Ap + k0 + 8);
            bv = *(const float4*)(Bp + k0 + 8);
        }
        #pragma unroll
        for (int kk = 0; kk < 8; ++kk) {
            float a[8], bb[8];
            #pragma unroll
            for (int i = 0; i < 8; ++i) a[i]  = As[kk][tr + 16 * i];
            #pragma unroll
            for (int j = 0; j < 8; ++j) bb[j] = Bs[kk][tc + 16 * j];
            #pragma unroll
            for (int i = 0; i < 8; ++i)
                #pragma unroll
                for (int j = 0; j < 8; ++j)
                    acc[i][j] = fmaf(a[i], bb[j], acc[i][j]);
        }
    }

    #pragma unroll
    for (int i = 0; i < 8; ++i) {
        int m = bm + tr + 16 * i;
        #pragma unroll
        for (int j = 0; j < 8; ++j) {
            int n = bn + tc + 16 * j;
            float d2 = fminf(fmaxf(acc[i][j] * 0.5f, -2.f), 2.f);
            C[(size_t)m * GN + n] = H[(size_t)m * GN + n] + d2;
        }
    }
}

// ---------------------------------------------------------------------
extern "C" void kernel_launch(void* const* d_in, const int* in_sizes, int n_in,
                              void* d_out, int out_size) {
    const float* h    = (const float*)d_in[0];
    const int*   mask = (const int*)  d_in[1];
    const float* lng  = (const float*)d_in[2];
    const float* lnb  = (const float*)d_in[3];
    const float* Wout = (const float*)d_in[4];
    const float* Wnm  = (const float*)d_in[5];
    const float* bnm  = (const float*)d_in[6];
    const float* Wwg  = (const float*)d_in[7];
    const float* bwg  = (const float*)d_in[8];
    float* out = (float*)d_out;

    cudaFuncSetAttribute(chunk_kernel,
                         cudaFuncAttributeMaxDynamicSharedMemorySize,
                         SMEM_BYTES);

    init_kernel<<<448, 256>>>();
    pre_kernel<<<Bq * NCq, 256>>>(h, Wnm, Wwg);

    for (int c = 0; c < NCq; ++c)
        chunk_kernel<<<72, 256, SMEM_BYTES>>>(h, mask, bnm, Wwg, bwg, c);

    mbuild_kernel<<<NCq * 56, 256>>>(h);
    stats_kernel<<<GM / 8, 256>>>();

    dim3 grid(GN / 128, GM / 128);
    gemm_kernel<<<grid, 256>>>(Wout, h, lng, lnb, out);
}